// round 10
// baseline (speedup 1.0000x reference)
#include <cuda_runtime.h>
#include <cuda_fp16.h>
#include <cstdint>

#define NN      50000
#define IN_C    128
#define HID     256
#define OUT_C   40
#define NLAYERS 4
#define NGROUPS 2
#define GC      128
#define NEDGES  600000
#define LN_EPS  1e-5f
#define SCAN_BLKS 196
#define GRID_BLKS 296   // exactly 2 blocks/SM on 148 SMs — all co-resident

// Scratch (device globals: allocation-free)
__device__ float  g_h[(size_t)NN * HID];
__device__ __half g_z[(size_t)NN * GC];
__device__ float2 g_stats[NN];
__device__ __half g_wt1[HID * IN_C];
__device__ __half g_wtc[8 * GC * GC];
__device__ __half g_wt2[128 * HID];            // lin2_w padded 40->128 rows (pad stays 0)
__device__ int    g_cnt[NN];
__device__ int    g_cur[NN];
__device__ int    g_off[NN + 1];
__device__ int    g_part[SCAN_BLKS];
__device__ int2   g_csr[NEDGES];
__device__ int    g_is64;
__device__ int    g_bar_cnt;
__device__ int    g_bar_flag;

__device__ __forceinline__ uint32_t h2_as_u32(__half2 h)
{
    return *reinterpret_cast<uint32_t*>(&h);
}

// ---------------------------------------------------------------------------
// Global sense-reversing barrier. All GRID_BLKS blocks are co-resident
// (smem-limited to 2/SM), so spinning is deadlock-free. Works across graph
// replays: sense is read at kernel entry, before any flip can occur.
// ---------------------------------------------------------------------------
__device__ __forceinline__ void grid_barrier(int& sense)
{
    __syncthreads();
    if (threadIdx.x == 0) {
        __threadfence();
        int old = atomicAdd(&g_bar_cnt, 1);
        if (old == GRID_BLKS - 1) {
            g_bar_cnt = 0;
            __threadfence();
            atomicExch(&g_bar_flag, sense ^ 1);
        } else {
            while (atomicAdd(&g_bar_flag, 0) == sense) __nanosleep(64);
        }
        __threadfence();
    }
    __syncthreads();
    sense ^= 1;
}

// ---------------------------------------------------------------------------
// Weight transpose: src fp32 [K][N] (batched) -> dst fp16 [N][K]
// ---------------------------------------------------------------------------
__global__ __launch_bounds__(256) void transpose_w_kernel(
    const float* __restrict__ src, __half* __restrict__ dst, int K, int N)
{
    __shared__ float tile[32][33];
    int b  = blockIdx.z;
    const float* s = src + (size_t)b * K * N;
    __half*      d = dst + (size_t)b * K * N;
    int k0 = blockIdx.y * 32, n0 = blockIdx.x * 32;
    int tx = threadIdx.x & 31, ty = threadIdx.x >> 5;
#pragma unroll
    for (int j = ty; j < 32; j += 8) {
        int k = k0 + j, n = n0 + tx;
        tile[j][tx] = (k < K && n < N) ? s[(size_t)k * N + n] : 0.f;
    }
    __syncthreads();
#pragma unroll
    for (int j = ty; j < 32; j += 8) {
        int n = n0 + j, k = k0 + tx;
        if (n < N && k < K) d[(size_t)n * K + k] = __float2half(tile[tx][j]);
    }
}

// ---------------------------------------------------------------------------
// Edge-index dtype detection (int64 vs int32)
// ---------------------------------------------------------------------------
__global__ void detect_idx_kernel(const int* __restrict__ ei32)
{
    __shared__ int nz;
    if (threadIdx.x == 0) nz = 0;
    __syncthreads();
    int bad = 0;
    for (int i = threadIdx.x; i < 2048; i += blockDim.x)
        if (ei32[2 * i + 1] != 0) bad = 1;
    if (bad) atomicOr(&nz, 1);
    __syncthreads();
    if (threadIdx.x == 0) g_is64 = (nz == 0) ? 1 : 0;
}

__device__ __forceinline__ int load_idx(const void* ei, int pos)
{
    if (g_is64) return (int)((const long long*)ei)[pos];
    return ((const int*)ei)[pos];
}

// ---------------------------------------------------------------------------
// CSR build
// ---------------------------------------------------------------------------
__global__ __launch_bounds__(256) void zero_cnt_kernel()
{
    int i = blockIdx.x * blockDim.x + threadIdx.x;
    if (i < NN) { g_cnt[i] = 0; g_cur[i] = 0; }
}

__global__ __launch_bounds__(256) void hist_kernel(const void* __restrict__ ei)
{
    int e = blockIdx.x * blockDim.x + threadIdx.x;
    if (e < NEDGES) atomicAdd(&g_cnt[load_idx(ei, NEDGES + e)], 1);
}

__global__ __launch_bounds__(256) void scan_partial_kernel()
{
    __shared__ int sm[256];
    int i = blockIdx.x * 256 + threadIdx.x;
    int v = (i < NN) ? g_cnt[i] : 0;
    sm[threadIdx.x] = v;
    __syncthreads();
#pragma unroll
    for (int o = 128; o; o >>= 1) {
        if (threadIdx.x < o) sm[threadIdx.x] += sm[threadIdx.x + o];
        __syncthreads();
    }
    if (threadIdx.x == 0) g_part[blockIdx.x] = sm[0];
}

__global__ __launch_bounds__(256) void scan_blocks_kernel()
{
    __shared__ int sm[256];
    int t = threadIdx.x;
    int v = (t < SCAN_BLKS) ? g_part[t] : 0;
    sm[t] = v;
    __syncthreads();
#pragma unroll
    for (int o = 1; o < 256; o <<= 1) {
        int u = (t >= o) ? sm[t - o] : 0;
        __syncthreads();
        sm[t] += u;
        __syncthreads();
    }
    if (t < SCAN_BLKS) g_part[t] = sm[t] - v;
}

__global__ __launch_bounds__(256) void scan_final_kernel()
{
    __shared__ int sm[256];
    int t = threadIdx.x;
    int i = blockIdx.x * 256 + t;
    int v = (i < NN) ? g_cnt[i] : 0;
    sm[t] = v;
    __syncthreads();
#pragma unroll
    for (int o = 1; o < 256; o <<= 1) {
        int u = (t >= o) ? sm[t - o] : 0;
        __syncthreads();
        sm[t] += u;
        __syncthreads();
    }
    if (i <= NN) g_off[i] = g_part[blockIdx.x] + sm[t] - v;
}

__global__ __launch_bounds__(256) void fill_kernel(
    const void* __restrict__ ei, const float* __restrict__ ew)
{
    int e = blockIdx.x * blockDim.x + threadIdx.x;
    if (e >= NEDGES) return;
    int srcv = load_idx(ei, e);
    int d    = load_idx(ei, NEDGES + e);
    int pos = g_off[d] + atomicAdd(&g_cur[d], 1);
    g_csr[pos] = make_int2(srcv, __float_as_int(ew[e]));
}

// ---------------------------------------------------------------------------
// fp16 MMA helper
// ---------------------------------------------------------------------------
__device__ __forceinline__ void mma_f16(float* c, const uint32_t* a,
                                        uint32_t b0, uint32_t b1)
{
    asm volatile(
        "mma.sync.aligned.m16n8k16.row.col.f32.f16.f16.f32 "
        "{%0,%1,%2,%3}, {%4,%5,%6,%7}, {%8,%9}, {%0,%1,%2,%3};"
        : "+f"(c[0]), "+f"(c[1]), "+f"(c[2]), "+f"(c[3])
        : "r"(a[0]), "r"(a[1]), "r"(a[2]), "r"(a[3]), "r"(b0), "r"(b1));
}

// ---------------------------------------------------------------------------
// Standalone weight-resident persistent GEMM (for lin1 / lin2), as in R9.
// ---------------------------------------------------------------------------
template<bool LN, bool HALF_OUT, int KD>
__global__ __launch_bounds__(256, KD == 128 ? 2 : 1) void gemm_f16_kernel(
    const float* __restrict__ A, int lda,
    const __half* __restrict__ Wt,
    const float* __restrict__ bias, void* __restrict__ Cv, int ldc,
    int nrows, int ncol_lim,
    const float* __restrict__ gamma, const float* __restrict__ beta)
{
    constexpr int PF = KD / 2 + 4;
    constexpr int AI = KD / 8;
    constexpr int BI = KD / 16;

    extern __shared__ uint32_t smem[];
    uint32_t* Bs  = smem;
    uint32_t* As0 = smem + 128 * PF;
    uint32_t* As1 = As0 + 128 * PF;

    const int tid  = threadIdx.x;
    const int wid  = tid >> 5;
    const int lane = tid & 31;
    const int gid  = lane >> 2;
    const int tig  = lane & 3;
    const int wm   = (wid & 3) * 32;
    const int wn   = (wid >> 2) * 64;
    const int colblk = blockIdx.y * 128;
    const int NRB  = (nrows + 127) >> 7;

#pragma unroll
    for (int i = 0; i < BI; i++) {
        int q   = tid + i * 256;
        int n   = q / (KD / 8);
        int kh8 = (q % (KD / 8)) * 8;
        uint4 v = *(const uint4*)(Wt + (size_t)(colblk + n) * KD + kh8);
        *(uint4*)&Bs[n * PF + (kh8 >> 1)] = v;
    }

    uint32_t ra[AI][2];

    auto loadA = [&](int rb) {
        int rowblk = rb * 128;
#pragma unroll
        for (int i = 0; i < AI; i++) {
            int q  = tid + i * 256;
            int r  = q / (KD / 4);
            int c4 = (q % (KD / 4)) * 4;
            int grow = rowblk + r;
            float4 v = make_float4(0.f, 0.f, 0.f, 0.f);
            if (grow < nrows) {
                v = *(const float4*)(A + (size_t)grow * lda + c4);
                if (LN) {
                    float2 st = g_stats[grow];
                    float4 g4 = *(const float4*)(gamma + c4);
                    float4 b4 = *(const float4*)(beta + c4);
                    v.x = fmaxf((v.x - st.x) * st.y * g4.x + b4.x, 0.f);
                    v.y = fmaxf((v.y - st.x) * st.y * g4.y + b4.y, 0.f);
                    v.z = fmaxf((v.z - st.x) * st.y * g4.z + b4.z, 0.f);
                    v.w = fmaxf((v.w - st.x) * st.y * g4.w + b4.w, 0.f);
                }
            }
            ra[i][0] = h2_as_u32(__floats2half2_rn(v.x, v.y));
            ra[i][1] = h2_as_u32(__floats2half2_rn(v.z, v.w));
        }
    };

    auto storeA = [&](uint32_t* As) {
#pragma unroll
        for (int i = 0; i < AI; i++) {
            int q  = tid + i * 256;
            int r  = q / (KD / 4);
            int c4 = (q % (KD / 4)) * 4;
            *(uint2*)&As[r * PF + (c4 >> 1)] = make_uint2(ra[i][0], ra[i][1]);
        }
    };

    float c[2][8][4];

    int rb = blockIdx.x;
    if (rb >= NRB) return;
    loadA(rb);
    storeA(As0);
    __syncthreads();

    int buf = 0;
    for (;;) {
        int rb_next = rb + gridDim.x;
        bool more = rb_next < NRB;
        if (more) loadA(rb_next);

#pragma unroll
        for (int mt = 0; mt < 2; mt++)
#pragma unroll
            for (int nt = 0; nt < 8; nt++)
#pragma unroll
                for (int r = 0; r < 4; r++) c[mt][nt][r] = 0.f;

        uint32_t* As = buf ? As1 : As0;
#pragma unroll
        for (int ks = 0; ks < KD / 16; ks++) {
            int kh = ks * 8;
            uint32_t a[2][4];
#pragma unroll
            for (int mt = 0; mt < 2; mt++) {
                int m = wm + mt * 16 + gid;
                a[mt][0] = As[m * PF + kh + tig];
                a[mt][1] = As[(m + 8) * PF + kh + tig];
                a[mt][2] = As[m * PF + kh + tig + 4];
                a[mt][3] = As[(m + 8) * PF + kh + tig + 4];
            }
#pragma unroll
            for (int nt = 0; nt < 8; nt++) {
                int n = wn + nt * 8 + gid;
                uint32_t b0 = Bs[n * PF + kh + tig];
                uint32_t b1 = Bs[n * PF + kh + tig + 4];
                mma_f16(c[0][nt], a[0], b0, b1);
                mma_f16(c[1][nt], a[1], b0, b1);
            }
        }

        int rowblk = rb * 128;
#pragma unroll
        for (int mt = 0; mt < 2; mt++) {
            int row0 = rowblk + wm + mt * 16 + gid;
            int row1 = row0 + 8;
#pragma unroll
            for (int nt = 0; nt < 8; nt++) {
                int col = colblk + wn + nt * 8 + 2 * tig;
                if (col >= ncol_lim) continue;
                float bx = 0.f, by = 0.f;
                if (bias != nullptr) { bx = bias[col]; by = bias[col + 1]; }
                if (HALF_OUT) {
                    __half* C = (__half*)Cv;
                    if (row0 < nrows)
                        *(__half2*)(C + (size_t)row0 * ldc + col) =
                            __floats2half2_rn(c[mt][nt][0] + bx, c[mt][nt][1] + by);
                    if (row1 < nrows)
                        *(__half2*)(C + (size_t)row1 * ldc + col) =
                            __floats2half2_rn(c[mt][nt][2] + bx, c[mt][nt][3] + by);
                } else {
                    float* C = (float*)Cv;
                    if (row0 < nrows)
                        *(float2*)(C + (size_t)row0 * ldc + col) =
                            make_float2(c[mt][nt][0] + bx, c[mt][nt][1] + by);
                    if (row1 < nrows)
                        *(float2*)(C + (size_t)row1 * ldc + col) =
                            make_float2(c[mt][nt][2] + bx, c[mt][nt][3] + by);
                }
            }
        }

        if (!more) break;
        buf ^= 1;
        storeA(buf ? As1 : As0);
        __syncthreads();
        rb = rb_next;
    }
}

// ---------------------------------------------------------------------------
// CSR gather edge accumulate
// ---------------------------------------------------------------------------
__device__ __forceinline__ void acc_edge(float4& acc, const __half* z,
                                         int2 m, int lane)
{
    float w = __int_as_float(m.y);
    uint2 u = *(const uint2*)(z + (size_t)m.x * GC + lane * 4);
    float2 lo = __half22float2(*(const __half2*)&u.x);
    float2 hi = __half22float2(*(const __half2*)&u.y);
    acc.x = fmaf(w, lo.x, acc.x); acc.y = fmaf(w, lo.y, acc.y);
    acc.z = fmaf(w, hi.x, acc.z); acc.w = fmaf(w, hi.y, acc.w);
}

// ---------------------------------------------------------------------------
// MEGAKERNEL: stats + 8 x (conv GEMM -> gather), phases separated by a
// global spin barrier. 296 blocks, 2/SM, 104 KB smem each.
// ---------------------------------------------------------------------------
__global__ __launch_bounds__(256, 2) void mega_kernel(
    const float* __restrict__ norm_g, const float* __restrict__ norm_b,
    const float* __restrict__ conv_b)
{
    constexpr int KD = 128, PF = KD / 2 + 4, AI = KD / 8, BI = KD / 16;
    extern __shared__ uint32_t smem[];
    uint32_t* Bs  = smem;
    uint32_t* As0 = smem + 128 * PF;
    uint32_t* As1 = As0 + 128 * PF;

    const int tid  = threadIdx.x;
    const int wid  = tid >> 5;
    const int lane = tid & 31;
    const int gid  = lane >> 2;
    const int tig  = lane & 3;
    const int wm   = (wid & 3) * 32;
    const int wn   = (wid >> 2) * 64;
    const int NRB  = (NN + 127) >> 7;       // 391

    float*  h = g_h;
    __half* z = g_z;

    int sense = atomicAdd(&g_bar_flag, 0);  // uniform pre-flip read

    // ---- phase 0: LN stats over h[:, GC:256] (input to first GEMM) ----
    for (int row = blockIdx.x * 8 + wid; row < NN; row += GRID_BLKS * 8) {
        float4 v = ((const float4*)(h + (size_t)row * HID + GC))[lane];
        float s  = v.x + v.y + v.z + v.w;
        float sq = v.x * v.x + v.y * v.y + v.z * v.z + v.w * v.w;
#pragma unroll
        for (int o = 16; o; o >>= 1) {
            s  += __shfl_xor_sync(0xffffffffu, s, o);
            sq += __shfl_xor_sync(0xffffffffu, sq, o);
        }
        if (lane == 0) {
            float mu  = s * (1.f / 128.f);
            float var = sq * (1.f / 128.f) - mu * mu;
            g_stats[row] = make_float2(mu, rsqrtf(var + LN_EPS));
        }
    }
    grid_barrier(sense);

    for (int bidx = 0; bidx < NLAYERS * NGROUPS; bidx++) {
        const int in_ofs  = (bidx & 1) ? 0 : GC;
        const int out_ofs = (bidx & 1) * GC;
        const __half* Wt    = g_wtc + (size_t)bidx * GC * GC;
        const float*  gamma = norm_g + bidx * GC;
        const float*  beta  = norm_b + bidx * GC;
        const float*  bias  = conv_b + bidx * GC;
        const bool    full  = (bidx == NLAYERS * NGROUPS - 1);

        // ================= GEMM phase =================
#pragma unroll
        for (int i = 0; i < BI; i++) {
            int q   = tid + i * 256;
            int n   = q / (KD / 8);
            int kh8 = (q % (KD / 8)) * 8;
            uint4 v = *(const uint4*)(Wt + (size_t)n * KD + kh8);
            *(uint4*)&Bs[n * PF + (kh8 >> 1)] = v;
        }

        uint32_t ra[AI][2];
        auto loadA = [&](int rb) {
            int rowblk = rb * 128;
#pragma unroll
            for (int i = 0; i < AI; i++) {
                int q  = tid + i * 256;
                int r  = q / (KD / 4);
                int c4 = (q % (KD / 4)) * 4;
                int grow = rowblk + r;
                float4 v = make_float4(0.f, 0.f, 0.f, 0.f);
                if (grow < NN) {
                    v = *(const float4*)(h + (size_t)grow * HID + in_ofs + c4);
                    float2 st = g_stats[grow];
                    float4 g4 = *(const float4*)(gamma + c4);
                    float4 b4 = *(const float4*)(beta + c4);
                    v.x = fmaxf((v.x - st.x) * st.y * g4.x + b4.x, 0.f);
                    v.y = fmaxf((v.y - st.x) * st.y * g4.y + b4.y, 0.f);
                    v.z = fmaxf((v.z - st.x) * st.y * g4.z + b4.z, 0.f);
                    v.w = fmaxf((v.w - st.x) * st.y * g4.w + b4.w, 0.f);
                }
                ra[i][0] = h2_as_u32(__floats2half2_rn(v.x, v.y));
                ra[i][1] = h2_as_u32(__floats2half2_rn(v.z, v.w));
            }
        };
        auto storeA = [&](uint32_t* As) {
#pragma unroll
            for (int i = 0; i < AI; i++) {
                int q  = tid + i * 256;
                int r  = q / (KD / 4);
                int c4 = (q % (KD / 4)) * 4;
                *(uint2*)&As[r * PF + (c4 >> 1)] = make_uint2(ra[i][0], ra[i][1]);
            }
        };

        float c[2][8][4];
        int rb = blockIdx.x;
        loadA(rb);
        storeA(As0);
        __syncthreads();

        int buf = 0;
        for (;;) {
            int rb_next = rb + GRID_BLKS;
            bool more = rb_next < NRB;
            if (more) loadA(rb_next);

#pragma unroll
            for (int mt = 0; mt < 2; mt++)
#pragma unroll
                for (int nt = 0; nt < 8; nt++)
#pragma unroll
                    for (int r = 0; r < 4; r++) c[mt][nt][r] = 0.f;

            uint32_t* As = buf ? As1 : As0;
#pragma unroll
            for (int ks = 0; ks < KD / 16; ks++) {
                int kh = ks * 8;
                uint32_t a[2][4];
#pragma unroll
                for (int mt = 0; mt < 2; mt++) {
                    int m = wm + mt * 16 + gid;
                    a[mt][0] = As[m * PF + kh + tig];
                    a[mt][1] = As[(m + 8) * PF + kh + tig];
                    a[mt][2] = As[m * PF + kh + tig + 4];
                    a[mt][3] = As[(m + 8) * PF + kh + tig + 4];
                }
#pragma unroll
                for (int nt = 0; nt < 8; nt++) {
                    int n = wn + nt * 8 + gid;
                    uint32_t b0 = Bs[n * PF + kh + tig];
                    uint32_t b1 = Bs[n * PF + kh + tig + 4];
                    mma_f16(c[0][nt], a[0], b0, b1);
                    mma_f16(c[1][nt], a[1], b0, b1);
                }
            }

            int rowblk = rb * 128;
#pragma unroll
            for (int mt = 0; mt < 2; mt++) {
                int row0 = rowblk + wm + mt * 16 + gid;
                int row1 = row0 + 8;
#pragma unroll
                for (int nt = 0; nt < 8; nt++) {
                    int col = wn + nt * 8 + 2 * tig;
                    if (row0 < NN)
                        *(__half2*)(z + (size_t)row0 * GC + col) =
                            __floats2half2_rn(c[mt][nt][0], c[mt][nt][1]);
                    if (row1 < NN)
                        *(__half2*)(z + (size_t)row1 * GC + col) =
                            __floats2half2_rn(c[mt][nt][2], c[mt][nt][3]);
                }
            }

            if (!more) break;
            buf ^= 1;
            storeA(buf ? As1 : As0);
            __syncthreads();
            rb = rb_next;
        }

        grid_barrier(sense);   // z complete, visible to all

        // ================= gather phase =================
        for (int row = blockIdx.x * 8 + wid; row < NN; row += GRID_BLKS * 8) {
            float4 acc = ((const float4*)bias)[lane];
            int s = g_off[row], e = g_off[row + 1];
            int i = s;
            for (; i + 4 <= e; i += 4) {
                int2 m0 = g_csr[i];
                int2 m1 = g_csr[i + 1];
                int2 m2 = g_csr[i + 2];
                int2 m3 = g_csr[i + 3];
                acc_edge(acc, z, m0, lane);
                acc_edge(acc, z, m1, lane);
                acc_edge(acc, z, m2, lane);
                acc_edge(acc, z, m3, lane);
            }
            for (; i < e; i++)
                acc_edge(acc, z, g_csr[i], lane);

            float4* hp = (float4*)(h + (size_t)row * HID + out_ofs);
            float4 hv = hp[lane];
            hv.x += acc.x; hv.y += acc.y; hv.z += acc.z; hv.w += acc.w;
            hp[lane] = hv;

            float sm = hv.x + hv.y + hv.z + hv.w;
            float sq = hv.x * hv.x + hv.y * hv.y + hv.z * hv.z + hv.w * hv.w;
            float inv = 1.f / 128.f;
            if (full) {
                const float4* op = (const float4*)(h + (size_t)row * HID + (out_ofs ^ GC));
                float4 ov = op[lane];
                sm += ov.x + ov.y + ov.z + ov.w;
                sq += ov.x * ov.x + ov.y * ov.y + ov.z * ov.z + ov.w * ov.w;
                inv = 1.f / 256.f;
            }
#pragma unroll
            for (int o = 16; o; o >>= 1) {
                sm += __shfl_xor_sync(0xffffffffu, sm, o);
                sq += __shfl_xor_sync(0xffffffffu, sq, o);
            }
            if (lane == 0) {
                float mu  = sm * inv;
                float var = sq * inv - mu * mu;
                g_stats[row] = make_float2(mu, rsqrtf(var + LN_EPS));
            }
        }

        grid_barrier(sense);   // h + stats complete for next GEMM
    }
}

// ---------------------------------------------------------------------------
extern "C" void kernel_launch(void* const* d_in, const int* in_sizes, int n_in,
                              void* d_out, int out_size)
{
    const float* x       = (const float*)d_in[0];
    const void*  ei      = d_in[1];
    const float* ew      = (const float*)d_in[2];
    const float* lin1_w  = (const float*)d_in[3];
    const float* lin1_b  = (const float*)d_in[4];
    const float* lin2_w  = (const float*)d_in[5];
    const float* lin2_b  = (const float*)d_in[6];
    const float* norm_g  = (const float*)d_in[7];
    const float* norm_b  = (const float*)d_in[8];
    const float* conv_w  = (const float*)d_in[9];
    const float* conv_b  = (const float*)d_in[10];
    const float* fnorm_g = (const float*)d_in[11];
    const float* fnorm_b = (const float*)d_in[12];
    float*       out     = (float*)d_out;

    float  *h;
    __half *wt1, *wtc, *wt2;
    cudaGetSymbolAddress((void**)&h, g_h);
    cudaGetSymbolAddress((void**)&wt1, g_wt1);
    cudaGetSymbolAddress((void**)&wtc, g_wtc);
    cudaGetSymbolAddress((void**)&wt2, g_wt2);

    const int SMEM128 = 3 * 128 * (128 / 2 + 4) * 4;   // 104448 B
    const int SMEM256 = 3 * 128 * (256 / 2 + 4) * 4;   // 202752 B

    static cudaStream_t s_csr = nullptr;
    static cudaEvent_t  ev_fork = nullptr, ev_csr = nullptr;
    if (s_csr == nullptr) {
        cudaStreamCreateWithFlags(&s_csr, cudaStreamNonBlocking);
        cudaEventCreateWithFlags(&ev_fork, cudaEventDisableTiming);
        cudaEventCreateWithFlags(&ev_csr, cudaEventDisableTiming);
        cudaFuncSetAttribute((const void*)gemm_f16_kernel<false, false, 128>,
                             cudaFuncAttributeMaxDynamicSharedMemorySize, SMEM128);
        cudaFuncSetAttribute((const void*)gemm_f16_kernel<true, false, 256>,
                             cudaFuncAttributeMaxDynamicSharedMemorySize, SMEM256);
        cudaFuncSetAttribute((const void*)mega_kernel,
                             cudaFuncAttributeMaxDynamicSharedMemorySize, SMEM128);
    }

    const int E_BLKS = (NEDGES + 255) / 256;
    const int N_BLKS = (NN + 255) / 256;

    // Fork CSR build onto side stream
    detect_idx_kernel<<<1, 256>>>((const int*)ei);
    cudaEventRecord(ev_fork, 0);
    cudaStreamWaitEvent(s_csr, ev_fork, 0);
    zero_cnt_kernel<<<N_BLKS, 256, 0, s_csr>>>();
    hist_kernel<<<E_BLKS, 256, 0, s_csr>>>(ei);
    scan_partial_kernel<<<SCAN_BLKS, 256, 0, s_csr>>>();
    scan_blocks_kernel<<<1, 256, 0, s_csr>>>();
    scan_final_kernel<<<SCAN_BLKS, 256, 0, s_csr>>>();
    fill_kernel<<<E_BLKS, 256, 0, s_csr>>>(ei, ew);
    cudaEventRecord(ev_csr, s_csr);

    // Main stream: weight transposes, lin1
    transpose_w_kernel<<<dim3(HID / 32, IN_C / 32, 1), 256>>>(lin1_w, wt1, IN_C, HID);
    transpose_w_kernel<<<dim3(GC / 32, GC / 32, 8), 256>>>(conv_w, wtc, GC, GC);
    transpose_w_kernel<<<dim3(2, HID / 32, 1), 256>>>(lin2_w, wt2, HID, OUT_C);

    gemm_f16_kernel<false, false, 128><<<dim3(296, 2), 256, SMEM128>>>(
        x, IN_C, wt1, lin1_b, h, HID, NN, HID, nullptr, nullptr);

    // Join CSR, then the whole middle loop as ONE persistent kernel
    cudaStreamWaitEvent(0, ev_csr, 0);
    mega_kernel<<<GRID_BLKS, 256, SMEM128>>>(norm_g, norm_b, conv_b);

    // lin2 on tensor cores with fused final LN+ReLU
    gemm_f16_kernel<true, false, 256><<<dim3(148, 1), 256, SMEM256>>>(
        h, HID, wt2, lin2_b, out, OUT_C, NN, OUT_C, fnorm_g, fnorm_b);
}

// round 11
// speedup vs baseline: 1.6716x; 1.6716x over previous
#include <cuda_runtime.h>
#include <cuda_fp16.h>
#include <cstdint>

#define NN      50000
#define IN_C    128
#define HID     256
#define OUT_C   40
#define NLAYERS 4
#define NGROUPS 2
#define GC      128
#define NEDGES  600000
#define LN_EPS  1e-5f
#define SCAN_BLKS 196

// Scratch (device globals: allocation-free)
__device__ float  g_h[(size_t)NN * HID];
__device__ __half g_z[(size_t)NN * GC];
__device__ float2 g_stats[NN];
__device__ __half g_wt1[HID * IN_C];
__device__ __half g_wtc[8 * GC * GC];
__device__ __half g_wt2[128 * HID];            // lin2_w padded 40->128 rows (pad stays 0)
__device__ int    g_cnt[NN];
__device__ int    g_cur[NN];
__device__ int    g_off[NN + 1];
__device__ int    g_part[SCAN_BLKS];
__device__ int2   g_csr[NEDGES];
__device__ int    g_is64;

__device__ __forceinline__ uint32_t h2_as_u32(__half2 h)
{
    return *reinterpret_cast<uint32_t*>(&h);
}

// ---------------------------------------------------------------------------
// Weight transpose: src fp32 [K][N] (batched) -> dst fp16 [N][K]
// ---------------------------------------------------------------------------
__global__ __launch_bounds__(256) void transpose_w_kernel(
    const float* __restrict__ src, __half* __restrict__ dst, int K, int N)
{
    __shared__ float tile[32][33];
    int b  = blockIdx.z;
    const float* s = src + (size_t)b * K * N;
    __half*      d = dst + (size_t)b * K * N;
    int k0 = blockIdx.y * 32, n0 = blockIdx.x * 32;
    int tx = threadIdx.x & 31, ty = threadIdx.x >> 5;
#pragma unroll
    for (int j = ty; j < 32; j += 8) {
        int k = k0 + j, n = n0 + tx;
        tile[j][tx] = (k < K && n < N) ? s[(size_t)k * N + n] : 0.f;
    }
    __syncthreads();
#pragma unroll
    for (int j = ty; j < 32; j += 8) {
        int n = n0 + j, k = k0 + tx;
        if (n < N && k < K) d[(size_t)n * K + k] = __float2half(tile[tx][j]);
    }
}

// ---------------------------------------------------------------------------
// Edge-index dtype detection (int64 vs int32)
// ---------------------------------------------------------------------------
__global__ void detect_idx_kernel(const int* __restrict__ ei32)
{
    __shared__ int nz;
    if (threadIdx.x == 0) nz = 0;
    __syncthreads();
    int bad = 0;
    for (int i = threadIdx.x; i < 2048; i += blockDim.x)
        if (ei32[2 * i + 1] != 0) bad = 1;
    if (bad) atomicOr(&nz, 1);
    __syncthreads();
    if (threadIdx.x == 0) g_is64 = (nz == 0) ? 1 : 0;
}

__device__ __forceinline__ int load_idx(const void* ei, int pos)
{
    if (g_is64) return (int)((const long long*)ei)[pos];
    return ((const int*)ei)[pos];
}

// ---------------------------------------------------------------------------
// CSR build
// ---------------------------------------------------------------------------
__global__ __launch_bounds__(256) void zero_cnt_kernel()
{
    int i = blockIdx.x * blockDim.x + threadIdx.x;
    if (i < NN) { g_cnt[i] = 0; g_cur[i] = 0; }
}

__global__ __launch_bounds__(256) void hist_kernel(const void* __restrict__ ei)
{
    int e = blockIdx.x * blockDim.x + threadIdx.x;
    if (e < NEDGES) atomicAdd(&g_cnt[load_idx(ei, NEDGES + e)], 1);
}

__global__ __launch_bounds__(256) void scan_partial_kernel()
{
    __shared__ int sm[256];
    int i = blockIdx.x * 256 + threadIdx.x;
    int v = (i < NN) ? g_cnt[i] : 0;
    sm[threadIdx.x] = v;
    __syncthreads();
#pragma unroll
    for (int o = 128; o; o >>= 1) {
        if (threadIdx.x < o) sm[threadIdx.x] += sm[threadIdx.x + o];
        __syncthreads();
    }
    if (threadIdx.x == 0) g_part[blockIdx.x] = sm[0];
}

__global__ __launch_bounds__(256) void scan_blocks_kernel()
{
    __shared__ int sm[256];
    int t = threadIdx.x;
    int v = (t < SCAN_BLKS) ? g_part[t] : 0;
    sm[t] = v;
    __syncthreads();
#pragma unroll
    for (int o = 1; o < 256; o <<= 1) {
        int u = (t >= o) ? sm[t - o] : 0;
        __syncthreads();
        sm[t] += u;
        __syncthreads();
    }
    if (t < SCAN_BLKS) g_part[t] = sm[t] - v;
}

__global__ __launch_bounds__(256) void scan_final_kernel()
{
    __shared__ int sm[256];
    int t = threadIdx.x;
    int i = blockIdx.x * 256 + t;
    int v = (i < NN) ? g_cnt[i] : 0;
    sm[t] = v;
    __syncthreads();
#pragma unroll
    for (int o = 1; o < 256; o <<= 1) {
        int u = (t >= o) ? sm[t - o] : 0;
        __syncthreads();
        sm[t] += u;
        __syncthreads();
    }
    if (i <= NN) g_off[i] = g_part[blockIdx.x] + sm[t] - v;
}

__global__ __launch_bounds__(256) void fill_kernel(
    const void* __restrict__ ei, const float* __restrict__ ew)
{
    int e = blockIdx.x * blockDim.x + threadIdx.x;
    if (e >= NEDGES) return;
    int srcv = load_idx(ei, e);
    int d    = load_idx(ei, NEDGES + e);
    int pos = g_off[d] + atomicAdd(&g_cur[d], 1);
    g_csr[pos] = make_int2(srcv, __float_as_int(ew[e]));
}

// ---------------------------------------------------------------------------
// fp16 MMA + ldmatrix helpers
// ---------------------------------------------------------------------------
__device__ __forceinline__ void mma_f16(float* c, const uint32_t* a,
                                        uint32_t b0, uint32_t b1)
{
    asm volatile(
        "mma.sync.aligned.m16n8k16.row.col.f32.f16.f16.f32 "
        "{%0,%1,%2,%3}, {%4,%5,%6,%7}, {%8,%9}, {%0,%1,%2,%3};"
        : "+f"(c[0]), "+f"(c[1]), "+f"(c[2]), "+f"(c[3])
        : "r"(a[0]), "r"(a[1]), "r"(a[2]), "r"(a[3]), "r"(b0), "r"(b1));
}

__device__ __forceinline__ void ldsm_x4(uint32_t& r0, uint32_t& r1,
                                        uint32_t& r2, uint32_t& r3,
                                        uint32_t saddr)
{
    asm volatile(
        "ldmatrix.sync.aligned.m8n8.x4.shared.b16 {%0,%1,%2,%3}, [%4];"
        : "=r"(r0), "=r"(r1), "=r"(r2), "=r"(r3) : "r"(saddr));
}

// ---------------------------------------------------------------------------
// Weight-resident persistent fp16 GEMM (fp32 accum), K = KD (128 or 256).
// B loaded to smem ONCE per block; block loops over 128-row blocks with a
// full-K A double buffer (one __syncthreads per row-block). Fragment loads
// via ldmatrix.x4 (6 LDSM vs 24 LDS per warp-kstep). Fused LN+ReLU on A.
// Row pitch KD/2+4 u32 -> conflict-free LDSM (row stride 272B: 8-row phases
// hit disjoint 4-bank groups).
// ---------------------------------------------------------------------------
template<bool LN, bool HALF_OUT, int KD>
__global__ __launch_bounds__(256, KD == 128 ? 2 : 1) void gemm_f16_kernel(
    const float* __restrict__ A, int lda,
    const __half* __restrict__ Wt,
    const float* __restrict__ bias, void* __restrict__ Cv, int ldc,
    int nrows, int ncol_lim,
    const float* __restrict__ gamma, const float* __restrict__ beta)
{
    constexpr int PF = KD / 2 + 4;
    constexpr int AI = KD / 8;
    constexpr int BI = KD / 16;

    extern __shared__ uint32_t smem[];
    uint32_t* Bs  = smem;
    uint32_t* As0 = smem + 128 * PF;
    uint32_t* As1 = As0 + 128 * PF;

    const int tid  = threadIdx.x;
    const int wid  = tid >> 5;
    const int lane = tid & 31;
    const int gid  = lane >> 2;
    const int tig  = lane & 3;
    const int wm   = (wid & 3) * 32;
    const int wn   = (wid >> 2) * 64;
    const int colblk = blockIdx.y * 128;
    const int NRB  = (nrows + 127) >> 7;

    // ldmatrix lane addressing (bytes)
    const int lrow = lane & 15;
    const int lkof = (lane >> 4) * 4;                 // u32 offset for k+8 tiles
    const uint32_t bs_base  = (uint32_t)__cvta_generic_to_shared(Bs);
    const uint32_t as0_base = (uint32_t)__cvta_generic_to_shared(As0);
    const uint32_t as1_base = (uint32_t)__cvta_generic_to_shared(As1);
    uint32_t aoff[2], boff[4];
#pragma unroll
    for (int mt = 0; mt < 2; mt++)
        aoff[mt] = ((wm + mt * 16 + lrow) * PF + lkof) * 4;
#pragma unroll
    for (int p = 0; p < 4; p++)
        boff[p] = ((wn + p * 16 + lrow) * PF + lkof) * 4;

#pragma unroll
    for (int i = 0; i < BI; i++) {
        int q   = tid + i * 256;
        int n   = q / (KD / 8);
        int kh8 = (q % (KD / 8)) * 8;
        uint4 v = *(const uint4*)(Wt + (size_t)(colblk + n) * KD + kh8);
        *(uint4*)&Bs[n * PF + (kh8 >> 1)] = v;
    }

    uint32_t ra[AI][2];

    auto loadA = [&](int rb) {
        int rowblk = rb * 128;
#pragma unroll
        for (int i = 0; i < AI; i++) {
            int q  = tid + i * 256;
            int r  = q / (KD / 4);
            int c4 = (q % (KD / 4)) * 4;
            int grow = rowblk + r;
            float4 v = make_float4(0.f, 0.f, 0.f, 0.f);
            if (grow < nrows) {
                v = *(const float4*)(A + (size_t)grow * lda + c4);
                if (LN) {
                    float2 st = g_stats[grow];
                    float4 g4 = *(const float4*)(gamma + c4);
                    float4 b4 = *(const float4*)(beta + c4);
                    v.x = fmaxf((v.x - st.x) * st.y * g4.x + b4.x, 0.f);
                    v.y = fmaxf((v.y - st.x) * st.y * g4.y + b4.y, 0.f);
                    v.z = fmaxf((v.z - st.x) * st.y * g4.z + b4.z, 0.f);
                    v.w = fmaxf((v.w - st.x) * st.y * g4.w + b4.w, 0.f);
                }
            }
            ra[i][0] = h2_as_u32(__floats2half2_rn(v.x, v.y));
            ra[i][1] = h2_as_u32(__floats2half2_rn(v.z, v.w));
        }
    };

    auto storeA = [&](uint32_t* As) {
#pragma unroll
        for (int i = 0; i < AI; i++) {
            int q  = tid + i * 256;
            int r  = q / (KD / 4);
            int c4 = (q % (KD / 4)) * 4;
            *(uint2*)&As[r * PF + (c4 >> 1)] = make_uint2(ra[i][0], ra[i][1]);
        }
    };

    float c[2][8][4];

    int rb = blockIdx.x;
    if (rb >= NRB) return;
    loadA(rb);
    storeA(As0);
    __syncthreads();

    int buf = 0;
    for (;;) {
        int rb_next = rb + gridDim.x;
        bool more = rb_next < NRB;
        if (more) loadA(rb_next);

#pragma unroll
        for (int mt = 0; mt < 2; mt++)
#pragma unroll
            for (int nt = 0; nt < 8; nt++)
#pragma unroll
                for (int r = 0; r < 4; r++) c[mt][nt][r] = 0.f;

        const uint32_t as_base = buf ? as1_base : as0_base;
#pragma unroll
        for (int ks = 0; ks < KD / 16; ks++) {
            const uint32_t khb = ks * 32;          // 8 u32 = 32 bytes
            uint32_t a[2][4];
            ldsm_x4(a[0][0], a[0][1], a[0][2], a[0][3], as_base + aoff[0] + khb);
            ldsm_x4(a[1][0], a[1][1], a[1][2], a[1][3], as_base + aoff[1] + khb);
#pragma unroll
            for (int p = 0; p < 4; p++) {
                uint32_t b0A, b0B, b1A, b1B;
                ldsm_x4(b0A, b0B, b1A, b1B, bs_base + boff[p] + khb);
                mma_f16(c[0][2 * p],     a[0], b0A, b1A);
                mma_f16(c[1][2 * p],     a[1], b0A, b1A);
                mma_f16(c[0][2 * p + 1], a[0], b0B, b1B);
                mma_f16(c[1][2 * p + 1], a[1], b0B, b1B);
            }
        }

        int rowblk = rb * 128;
#pragma unroll
        for (int mt = 0; mt < 2; mt++) {
            int row0 = rowblk + wm + mt * 16 + gid;
            int row1 = row0 + 8;
#pragma unroll
            for (int nt = 0; nt < 8; nt++) {
                int col = colblk + wn + nt * 8 + 2 * tig;
                if (col >= ncol_lim) continue;
                float bx = 0.f, by = 0.f;
                if (bias != nullptr) { bx = bias[col]; by = bias[col + 1]; }
                if (HALF_OUT) {
                    __half* C = (__half*)Cv;
                    if (row0 < nrows)
                        *(__half2*)(C + (size_t)row0 * ldc + col) =
                            __floats2half2_rn(c[mt][nt][0] + bx, c[mt][nt][1] + by);
                    if (row1 < nrows)
                        *(__half2*)(C + (size_t)row1 * ldc + col) =
                            __floats2half2_rn(c[mt][nt][2] + bx, c[mt][nt][3] + by);
                } else {
                    float* C = (float*)Cv;
                    if (row0 < nrows)
                        *(float2*)(C + (size_t)row0 * ldc + col) =
                            make_float2(c[mt][nt][0] + bx, c[mt][nt][1] + by);
                    if (row1 < nrows)
                        *(float2*)(C + (size_t)row1 * ldc + col) =
                            make_float2(c[mt][nt][2] + bx, c[mt][nt][3] + by);
                }
            }
        }

        if (!more) break;
        buf ^= 1;
        storeA(buf ? As1 : As0);
        __syncthreads();
        rb = rb_next;
    }
}

// ---------------------------------------------------------------------------
// Standalone LN stats (only after lin1)
// ---------------------------------------------------------------------------
__global__ __launch_bounds__(256) void ln_stats_kernel(
    const float* __restrict__ h, int colofs)
{
    int row = blockIdx.x * 8 + (threadIdx.x >> 5);
    int lane = threadIdx.x & 31;
    if (row >= NN) return;
    float4 v = ((const float4*)(h + (size_t)row * HID + colofs))[lane];
    float s  = v.x + v.y + v.z + v.w;
    float sq = v.x * v.x + v.y * v.y + v.z * v.z + v.w * v.w;
#pragma unroll
    for (int o = 16; o; o >>= 1) {
        s  += __shfl_xor_sync(0xffffffffu, s, o);
        sq += __shfl_xor_sync(0xffffffffu, sq, o);
    }
    if (lane == 0) {
        float mu  = s * (1.f / 128.f);
        float var = sq * (1.f / 128.f) - mu * mu;
        g_stats[row] = make_float2(mu, rsqrtf(var + LN_EPS));
    }
}

// ---------------------------------------------------------------------------
// CSR gather (fp16 z) + bias + in-place h update + next-LN stats
// ---------------------------------------------------------------------------
__device__ __forceinline__ void acc_edge(float4& acc, const __half* z,
                                         int2 m, int lane)
{
    float w = __int_as_float(m.y);
    uint2 u = *(const uint2*)(z + (size_t)m.x * GC + lane * 4);
    float2 lo = __half22float2(*(const __half2*)&u.x);
    float2 hi = __half22float2(*(const __half2*)&u.y);
    acc.x = fmaf(w, lo.x, acc.x); acc.y = fmaf(w, lo.y, acc.y);
    acc.z = fmaf(w, hi.x, acc.z); acc.w = fmaf(w, hi.y, acc.w);
}

template<bool FULLSTATS>
__global__ __launch_bounds__(256) void gather_kernel(
    const __half* __restrict__ z, const float* __restrict__ bias,
    float* __restrict__ h, int out_ofs)
{
    int row = blockIdx.x * 8 + (threadIdx.x >> 5);
    int lane = threadIdx.x & 31;
    if (row >= NN) return;

    float4 acc = ((const float4*)bias)[lane];
    int s = g_off[row], e = g_off[row + 1];

    int i = s;
    for (; i + 4 <= e; i += 4) {
        int2 m0 = g_csr[i];
        int2 m1 = g_csr[i + 1];
        int2 m2 = g_csr[i + 2];
        int2 m3 = g_csr[i + 3];
        acc_edge(acc, z, m0, lane);
        acc_edge(acc, z, m1, lane);
        acc_edge(acc, z, m2, lane);
        acc_edge(acc, z, m3, lane);
    }
    for (; i < e; i++)
        acc_edge(acc, z, g_csr[i], lane);

    float4* hp = (float4*)(h + (size_t)row * HID + out_ofs);
    float4 hv = hp[lane];
    hv.x += acc.x; hv.y += acc.y; hv.z += acc.z; hv.w += acc.w;
    hp[lane] = hv;

    float sm = hv.x + hv.y + hv.z + hv.w;
    float sq = hv.x * hv.x + hv.y * hv.y + hv.z * hv.z + hv.w * hv.w;
    float inv = 1.f / 128.f;
    if (FULLSTATS) {
        const float4* op = (const float4*)(h + (size_t)row * HID + (out_ofs ^ GC));
        float4 ov = op[lane];
        sm += ov.x + ov.y + ov.z + ov.w;
        sq += ov.x * ov.x + ov.y * ov.y + ov.z * ov.z + ov.w * ov.w;
        inv = 1.f / 256.f;
    }
#pragma unroll
    for (int o = 16; o; o >>= 1) {
        sm += __shfl_xor_sync(0xffffffffu, sm, o);
        sq += __shfl_xor_sync(0xffffffffu, sq, o);
    }
    if (lane == 0) {
        float mu  = sm * inv;
        float var = sq * inv - mu * mu;
        g_stats[row] = make_float2(mu, rsqrtf(var + LN_EPS));
    }
}

// ---------------------------------------------------------------------------
extern "C" void kernel_launch(void* const* d_in, const int* in_sizes, int n_in,
                              void* d_out, int out_size)
{
    const float* x       = (const float*)d_in[0];
    const void*  ei      = d_in[1];
    const float* ew      = (const float*)d_in[2];
    const float* lin1_w  = (const float*)d_in[3];
    const float* lin1_b  = (const float*)d_in[4];
    const float* lin2_w  = (const float*)d_in[5];
    const float* lin2_b  = (const float*)d_in[6];
    const float* norm_g  = (const float*)d_in[7];
    const float* norm_b  = (const float*)d_in[8];
    const float* conv_w  = (const float*)d_in[9];
    const float* conv_b  = (const float*)d_in[10];
    const float* fnorm_g = (const float*)d_in[11];
    const float* fnorm_b = (const float*)d_in[12];
    float*       out     = (float*)d_out;

    float  *h;
    __half *z, *wt1, *wtc, *wt2;
    cudaGetSymbolAddress((void**)&h, g_h);
    cudaGetSymbolAddress((void**)&z, g_z);
    cudaGetSymbolAddress((void**)&wt1, g_wt1);
    cudaGetSymbolAddress((void**)&wtc, g_wtc);
    cudaGetSymbolAddress((void**)&wt2, g_wt2);

    const int SMEM128 = 3 * 128 * (128 / 2 + 4) * 4;   // 104448 B
    const int SMEM256 = 3 * 128 * (256 / 2 + 4) * 4;   // 202752 B

    static cudaStream_t s_csr = nullptr;
    static cudaEvent_t  ev_fork = nullptr, ev_csr = nullptr;
    if (s_csr == nullptr) {
        cudaStreamCreateWithFlags(&s_csr, cudaStreamNonBlocking);
        cudaEventCreateWithFlags(&ev_fork, cudaEventDisableTiming);
        cudaEventCreateWithFlags(&ev_csr, cudaEventDisableTiming);
        cudaFuncSetAttribute((const void*)gemm_f16_kernel<false, false, 128>,
                             cudaFuncAttributeMaxDynamicSharedMemorySize, SMEM128);
        cudaFuncSetAttribute((const void*)gemm_f16_kernel<true, true, 128>,
                             cudaFuncAttributeMaxDynamicSharedMemorySize, SMEM128);
        cudaFuncSetAttribute((const void*)gemm_f16_kernel<true, false, 256>,
                             cudaFuncAttributeMaxDynamicSharedMemorySize, SMEM256);
    }

    const int ROW_BLKS = NN / 8;             // 6250
    const int E_BLKS   = (NEDGES + 255) / 256;
    const int N_BLKS   = (NN + 255) / 256;

    // Fork CSR build (incl. dtype detect) entirely onto the side stream
    cudaEventRecord(ev_fork, 0);
    cudaStreamWaitEvent(s_csr, ev_fork, 0);
    detect_idx_kernel<<<1, 256, 0, s_csr>>>((const int*)ei);
    zero_cnt_kernel<<<N_BLKS, 256, 0, s_csr>>>();
    hist_kernel<<<E_BLKS, 256, 0, s_csr>>>(ei);
    scan_partial_kernel<<<SCAN_BLKS, 256, 0, s_csr>>>();
    scan_blocks_kernel<<<1, 256, 0, s_csr>>>();
    scan_final_kernel<<<SCAN_BLKS, 256, 0, s_csr>>>();
    fill_kernel<<<E_BLKS, 256, 0, s_csr>>>(ei, ew);
    cudaEventRecord(ev_csr, s_csr);

    // Main stream: weight transposes, lin1, first LN stats
    transpose_w_kernel<<<dim3(HID / 32, IN_C / 32, 1), 256>>>(lin1_w, wt1, IN_C, HID);
    transpose_w_kernel<<<dim3(GC / 32, GC / 32, 8), 256>>>(conv_w, wtc, GC, GC);
    transpose_w_kernel<<<dim3(2, HID / 32, 1), 256>>>(lin2_w, wt2, HID, OUT_C);

    gemm_f16_kernel<false, false, 128><<<dim3(296, 2), 256, SMEM128>>>(
        x, IN_C, wt1, lin1_b, h, HID, NN, HID, nullptr, nullptr);
    ln_stats_kernel<<<ROW_BLKS, 256>>>(h, GC);

    // Join: gathers need the CSR
    cudaStreamWaitEvent(0, ev_csr, 0);

    for (int l = 0; l < NLAYERS; l++) {
        for (int g = 0; g < NGROUPS; g++) {
            int in_ofs  = (g == 0) ? GC : 0;
            int out_ofs = g * GC;
            int bidx = l * NGROUPS + g;
            bool last = (bidx == NLAYERS * NGROUPS - 1);

            gemm_f16_kernel<true, true, 128><<<dim3(296, 1), 256, SMEM128>>>(
                h + in_ofs, HID, wtc + (size_t)bidx * GC * GC, nullptr,
                z, GC, NN, GC,
                norm_g + (size_t)bidx * GC, norm_b + (size_t)bidx * GC);
            if (last)
                gather_kernel<true><<<ROW_BLKS, 256>>>(z, conv_b + (size_t)bidx * GC, h, out_ofs);
            else
                gather_kernel<false><<<ROW_BLKS, 256>>>(z, conv_b + (size_t)bidx * GC, h, out_ofs);
        }
    }

    // lin2 on tensor cores with fused final LN+ReLU
    gemm_f16_kernel<true, false, 256><<<dim3(148, 1), 256, SMEM256>>>(
        h, HID, wt2, lin2_b, out, OUT_C, NN, OUT_C, fnorm_g, fnorm_b);
}